// round 2
// baseline (speedup 1.0000x reference)
#include <cuda_runtime.h>

// ---------------------------------------------------------------------------
// PAM module: dual attention (over W and over H) on template (64x64) and
// scene (128x128) maps. B=16, C=256, C8=32.
//
// All heavy ops are fp32 smem-tiled GEMMs (64x64 block tile, 16-deep K tile,
// 4x4 per-thread micro tile, 256 threads).
// ---------------------------------------------------------------------------

#define B_    16
#define C_    256
#define C8_   32
#define MROWS 320   // 32 (q) + 32 (k) + 256 (v)

// Scratch (device globals: allocation-free rule)
__device__ float g_qkv[(size_t)B_ * MROWS * 128 * 128];   // 335 MB, scene-sized
__device__ float g_att[(size_t)B_ * 128 * 128];           // logits / attention (in place)
__device__ float g_wc[MROWS * C_];
__device__ float g_bc[MROWS];

// ---------------------------------------------------------------------------
// Build stacked weight [320,256] and bias [320] for one branch.
// ---------------------------------------------------------------------------
__global__ void build_wc_kernel(const float* __restrict__ qw, const float* __restrict__ qb,
                                const float* __restrict__ kw, const float* __restrict__ kb,
                                const float* __restrict__ vw, const float* __restrict__ vb,
                                int br) {
    int i = blockIdx.x * blockDim.x + threadIdx.x;
    if (i < MROWS * C_) {
        int m = i / C_, k = i % C_;
        float val;
        if (m < 32)       val = qw[(size_t)br * 32 * C_ + m * C_ + k];
        else if (m < 64)  val = kw[(size_t)br * 32 * C_ + (m - 32) * C_ + k];
        else              val = vw[(size_t)br * C_ * C_ + (m - 64) * C_ + k];
        g_wc[i] = val;
    }
    if (i < MROWS) {
        g_bc[i] = (i < 32) ? qb[br * 32 + i]
                : (i < 64) ? kb[br * 32 + i - 32]
                           : vb[br * C_ + i - 64];
    }
}

// ---------------------------------------------------------------------------
// QKV projection: Out[b, m, n] = sum_k Wc[m,k] * X[b,k,n] + bc[m]
// M = 320, N = S*S, K = 256.  grid = (N/64, 5, B)
// ---------------------------------------------------------------------------
__global__ __launch_bounds__(256)
void proj_kernel(const float* __restrict__ x, int HW) {
    __shared__ float As[16][68];
    __shared__ float Bs[16][68];
    int b  = blockIdx.z;
    int m0 = blockIdx.y * 64;
    int n0 = blockIdx.x * 64;
    const float* Xb = x + (size_t)b * C_ * HW;
    float*       Ob = g_qkv + (size_t)b * MROWS * HW;

    int tid = threadIdx.x;
    int tx = tid & 15, ty = tid >> 4;
    float acc[4][4] = {};

    for (int k0 = 0; k0 < C_; k0 += 16) {
#pragma unroll
        for (int i = 0; i < 4; ++i) {           // Wc[m0+m][k0+k] -> As[k][m]
            int idx = tid + i * 256;
            int m = idx >> 4, k = idx & 15;
            As[k][m] = g_wc[(m0 + m) * C_ + k0 + k];
        }
#pragma unroll
        for (int i = 0; i < 4; ++i) {           // X[k0+k][n0+n] -> Bs[k][n] (coalesced)
            int idx = tid + i * 256;
            int n = idx & 63, k = idx >> 6;
            Bs[k][n] = Xb[(size_t)(k0 + k) * HW + n0 + n];
        }
        __syncthreads();
#pragma unroll
        for (int k = 0; k < 16; ++k) {
            float a[4], bb[4];
#pragma unroll
            for (int i = 0; i < 4; ++i) a[i]  = As[k][ty * 4 + i];
#pragma unroll
            for (int j = 0; j < 4; ++j) bb[j] = Bs[k][tx * 4 + j];
#pragma unroll
            for (int i = 0; i < 4; ++i)
#pragma unroll
                for (int j = 0; j < 4; ++j) acc[i][j] += a[i] * bb[j];
        }
        __syncthreads();
    }
#pragma unroll
    for (int i = 0; i < 4; ++i) {
        int m = m0 + ty * 4 + i;
        float bias = g_bc[m];
#pragma unroll
        for (int j = 0; j < 4; ++j)
            Ob[(size_t)m * HW + n0 + tx * 4 + j] = acc[i][j] + bias;
    }
}

// ---------------------------------------------------------------------------
// Logits over W: E[b,w,v] = sum_{o,h} Q[b,o,h,w] * K[b,o,h,v]
// Q flat = [F=C8*S, S] row-major.  M=N=S, K=F.  grid = (S/64, S/64, B)
// ---------------------------------------------------------------------------
__global__ __launch_bounds__(256)
void logits_w_kernel(int S) {
    __shared__ float As[16][68];
    __shared__ float Bs[16][68];
    int SS = S * S;
    int F  = C8_ * S;
    const float* Qb = g_qkv + (size_t)blockIdx.z * MROWS * SS;
    const float* Kb = Qb + (size_t)32 * SS;
    float*       Eb = g_att + (size_t)blockIdx.z * SS;

    int m0 = blockIdx.y * 64, n0 = blockIdx.x * 64;
    int tid = threadIdx.x;
    int tx = tid & 15, ty = tid >> 4;
    float acc[4][4] = {};

    for (int k0 = 0; k0 < F; k0 += 16) {
#pragma unroll
        for (int i = 0; i < 4; ++i) {
            int idx = tid + i * 256;
            int n = idx & 63, k = idx >> 6;
            As[k][n] = Qb[(size_t)(k0 + k) * S + m0 + n];
            Bs[k][n] = Kb[(size_t)(k0 + k) * S + n0 + n];
        }
        __syncthreads();
#pragma unroll
        for (int k = 0; k < 16; ++k) {
            float a[4], bb[4];
#pragma unroll
            for (int i = 0; i < 4; ++i) a[i]  = As[k][ty * 4 + i];
#pragma unroll
            for (int j = 0; j < 4; ++j) bb[j] = Bs[k][tx * 4 + j];
#pragma unroll
            for (int i = 0; i < 4; ++i)
#pragma unroll
                for (int j = 0; j < 4; ++j) acc[i][j] += a[i] * bb[j];
        }
        __syncthreads();
    }
#pragma unroll
    for (int i = 0; i < 4; ++i)
#pragma unroll
        for (int j = 0; j < 4; ++j)
            Eb[(size_t)(m0 + ty * 4 + i) * S + n0 + tx * 4 + j] = acc[i][j];
}

// ---------------------------------------------------------------------------
// Logits over H: E[b,h,v] = sum_{o,w} Q[b,o,h,w] * K[b,o,v,w]
// K-dim f = o*S + w (tiles never cross o since 16 | S). grid = (S/64, S/64, B)
// ---------------------------------------------------------------------------
__global__ __launch_bounds__(256)
void logits_h_kernel(int S) {
    __shared__ float As[16][68];
    __shared__ float Bs[16][68];
    int SS = S * S;
    int F  = C8_ * S;
    const float* Qb = g_qkv + (size_t)blockIdx.z * MROWS * SS;
    const float* Kb = Qb + (size_t)32 * SS;
    float*       Eb = g_att + (size_t)blockIdx.z * SS;

    int m0 = blockIdx.y * 64, n0 = blockIdx.x * 64;
    int tid = threadIdx.x;
    int tx = tid & 15, ty = tid >> 4;
    float acc[4][4] = {};

    for (int k0 = 0; k0 < F; k0 += 16) {
        int o  = k0 / S;
        int w0 = k0 % S;
        const float* Qo = Qb + (size_t)o * SS;
        const float* Ko = Kb + (size_t)o * SS;
#pragma unroll
        for (int i = 0; i < 4; ++i) {
            int idx = tid + i * 256;
            int k = idx & 15, m = idx >> 4;
            As[k][m] = Qo[(size_t)(m0 + m) * S + w0 + k];
            Bs[k][m] = Ko[(size_t)(n0 + m) * S + w0 + k];
        }
        __syncthreads();
#pragma unroll
        for (int k = 0; k < 16; ++k) {
            float a[4], bb[4];
#pragma unroll
            for (int i = 0; i < 4; ++i) a[i]  = As[k][ty * 4 + i];
#pragma unroll
            for (int j = 0; j < 4; ++j) bb[j] = Bs[k][tx * 4 + j];
#pragma unroll
            for (int i = 0; i < 4; ++i)
#pragma unroll
                for (int j = 0; j < 4; ++j) acc[i][j] += a[i] * bb[j];
        }
        __syncthreads();
    }
#pragma unroll
    for (int i = 0; i < 4; ++i)
#pragma unroll
        for (int j = 0; j < 4; ++j)
            Eb[(size_t)(m0 + ty * 4 + i) * S + n0 + tx * 4 + j] = acc[i][j];
}

// ---------------------------------------------------------------------------
// Row softmax in place on g_att: B*S rows of length S. blockDim = S.
// ---------------------------------------------------------------------------
__global__ void softmax_kernel(int S) {
    __shared__ float red[128];
    float* row = g_att + (size_t)blockIdx.x * S;
    int t = threadIdx.x;
    float v = row[t];
    red[t] = v;
    __syncthreads();
    for (int off = S >> 1; off > 0; off >>= 1) {
        if (t < off) red[t] = fmaxf(red[t], red[t + off]);
        __syncthreads();
    }
    float m = red[0];
    __syncthreads();
    float e = expf(v - m);
    red[t] = e;
    __syncthreads();
    for (int off = S >> 1; off > 0; off >>= 1) {
        if (t < off) red[t] += red[t + off];
        __syncthreads();
    }
    row[t] = e / red[0];
}

// ---------------------------------------------------------------------------
// Apply over W: out[b, m=(c*S+h), n=w] = 2*x + s * sum_v V[m,v]*A[w,v]
// V is rows [64,320) of QKV, contiguous [C*S, S]. grid = (S/64, C*S/64, B)
// ---------------------------------------------------------------------------
__global__ __launch_bounds__(256)
void apply_w_kernel(const float* __restrict__ x, float* __restrict__ out,
                    int S, const float* __restrict__ scalars, int br) {
    __shared__ float As[16][68];
    __shared__ float Bs[16][68];
    int SS = S * S;
    int b  = blockIdx.z;
    const float* Vb = g_qkv + (size_t)b * MROWS * SS + (size_t)64 * SS;
    const float* At = g_att + (size_t)b * SS;

    int m0 = blockIdx.y * 64, n0 = blockIdx.x * 64;
    int tid = threadIdx.x;
    int tx = tid & 15, ty = tid >> 4;
    float acc[4][4] = {};

    for (int k0 = 0; k0 < S; k0 += 16) {
#pragma unroll
        for (int i = 0; i < 4; ++i) {
            int idx = tid + i * 256;
            int k = idx & 15, m = idx >> 4;
            As[k][m] = Vb[(size_t)(m0 + m) * S + k0 + k];
            Bs[k][m] = At[(size_t)(n0 + m) * S + k0 + k];
        }
        __syncthreads();
#pragma unroll
        for (int k = 0; k < 16; ++k) {
            float a[4], bb[4];
#pragma unroll
            for (int i = 0; i < 4; ++i) a[i]  = As[k][ty * 4 + i];
#pragma unroll
            for (int j = 0; j < 4; ++j) bb[j] = Bs[k][tx * 4 + j];
#pragma unroll
            for (int i = 0; i < 4; ++i)
#pragma unroll
                for (int j = 0; j < 4; ++j) acc[i][j] += a[i] * bb[j];
        }
        __syncthreads();
    }
    float s = scalars[br];
#pragma unroll
    for (int i = 0; i < 4; ++i) {
        size_t base = (size_t)b * C_ * SS + (size_t)(m0 + ty * 4 + i) * S + n0 + tx * 4;
#pragma unroll
        for (int j = 0; j < 4; ++j)
            out[base + j] = 2.0f * x[base + j] + s * acc[i][j];
    }
}

// ---------------------------------------------------------------------------
// Apply over H: out[b,c,h,w] += s * sum_v A[h,v] * V[c,v,w]
// grid = (S/64, S/64, B*C)
// ---------------------------------------------------------------------------
__global__ __launch_bounds__(256)
void apply_h_kernel(float* __restrict__ out, int S,
                    const float* __restrict__ scalars, int br) {
    __shared__ float As[16][68];
    __shared__ float Bs[16][68];
    int SS = S * S;
    int bc = blockIdx.z;
    int b = bc / C_, c = bc % C_;
    const float* At = g_att + (size_t)b * SS;
    const float* Vc = g_qkv + (size_t)b * MROWS * SS + (size_t)(64 + c) * SS;

    int m0 = blockIdx.y * 64, n0 = blockIdx.x * 64;
    int tid = threadIdx.x;
    int tx = tid & 15, ty = tid >> 4;
    float acc[4][4] = {};

    for (int k0 = 0; k0 < S; k0 += 16) {
#pragma unroll
        for (int i = 0; i < 4; ++i) {
            int idx = tid + i * 256;
            {   // A[m][k] = At[(m0+m)*S + k0+k] -> As[k][m]
                int k = idx & 15, m = idx >> 4;
                As[k][m] = At[(size_t)(m0 + m) * S + k0 + k];
            }
            {   // B[k][n] = Vc[(k0+k)*S + n0+n] -> Bs[k][n] (coalesced)
                int n = idx & 63, k = idx >> 6;
                Bs[k][n] = Vc[(size_t)(k0 + k) * S + n0 + n];
            }
        }
        __syncthreads();
#pragma unroll
        for (int k = 0; k < 16; ++k) {
            float a[4], bb[4];
#pragma unroll
            for (int i = 0; i < 4; ++i) a[i]  = As[k][ty * 4 + i];
#pragma unroll
            for (int j = 0; j < 4; ++j) bb[j] = Bs[k][tx * 4 + j];
#pragma unroll
            for (int i = 0; i < 4; ++i)
#pragma unroll
                for (int j = 0; j < 4; ++j) acc[i][j] += a[i] * bb[j];
        }
        __syncthreads();
    }
    float s = scalars[br];
#pragma unroll
    for (int i = 0; i < 4; ++i) {
        size_t base = (size_t)b * C_ * SS + (size_t)c * SS
                    + (size_t)(m0 + ty * 4 + i) * S + n0 + tx * 4;
#pragma unroll
        for (int j = 0; j < 4; ++j)
            out[base + j] += s * acc[i][j];
    }
}

// ---------------------------------------------------------------------------
// Host-side orchestration
// ---------------------------------------------------------------------------
static void run_branch_pair(const float* x, int S, float* out,
                            int br_w, int br_h,
                            const float* qw, const float* qb,
                            const float* kw, const float* kb,
                            const float* vw, const float* vb,
                            const float* sc) {
    int SS = S * S;
    dim3 thr(256);

    // ---- over-W branch ----
    build_wc_kernel<<<(MROWS * C_ + 255) / 256, 256>>>(qw, qb, kw, kb, vw, vb, br_w);
    proj_kernel<<<dim3(SS / 64, MROWS / 64, B_), thr>>>(x, SS);
    logits_w_kernel<<<dim3(S / 64, S / 64, B_), thr>>>(S);
    softmax_kernel<<<B_ * S, S>>>(S);
    apply_w_kernel<<<dim3(S / 64, C_ * S / 64, B_), thr>>>(x, out, S, sc, br_w);

    // ---- over-H branch ----
    build_wc_kernel<<<(MROWS * C_ + 255) / 256, 256>>>(qw, qb, kw, kb, vw, vb, br_h);
    proj_kernel<<<dim3(SS / 64, MROWS / 64, B_), thr>>>(x, SS);
    logits_h_kernel<<<dim3(S / 64, S / 64, B_), thr>>>(S);
    softmax_kernel<<<B_ * S, S>>>(S);
    apply_h_kernel<<<dim3(S / 64, S / 64, B_ * C_), thr>>>(out, S, sc, br_h);
}

extern "C" void kernel_launch(void* const* d_in, const int* in_sizes, int n_in,
                              void* d_out, int out_size) {
    const float* tmap = (const float*)d_in[0];
    const float* smap = (const float*)d_in[1];
    const float* qw   = (const float*)d_in[2];
    const float* qb   = (const float*)d_in[3];
    const float* kw   = (const float*)d_in[4];
    const float* kb   = (const float*)d_in[5];
    const float* vw   = (const float*)d_in[6];
    const float* vb   = (const float*)d_in[7];
    const float* sc   = (const float*)d_in[8];

    float* tout = (float*)d_out;
    float* sout = tout + (size_t)B_ * C_ * 64 * 64;

    // template: branches 0 (over W), 2 (over H)
    run_branch_pair(tmap, 64, tout, 0, 2, qw, qb, kw, kb, vw, vb, sc);
    // scene: branches 1 (over W), 3 (over H)
    run_branch_pair(smap, 128, sout, 1, 3, qw, qb, kw, kb, vw, vb, sc);
}